// round 1
// baseline (speedup 1.0000x reference)
#include <cuda_runtime.h>
#include <math.h>
#include <stdint.h>

#define BB   512
#define TT   256
#define PP   61
#define HE   256
#define LATD 512
#define DECD 32
#define TBAR 16
#define NROWS (BB*TT)   // 131072

// ---------------- scratch (device globals; no allocation allowed) ----------------
__device__ float g_enc[(size_t)NROWS*512];     // (B*T, 2H) encoder outputs, 268MB
__device__ float g_h[2][2][BB*HE];             // [dir][parity][B*H] hidden double-buffer
__device__ float g_c[2][BB*HE];                // [dir][B*H] cell state
__device__ float g_emb[(size_t)BB*TBAR*DECD];  // conductor embeddings (row = b*16+bar)

__device__ __forceinline__ float sigmoidf_(float v){ return 1.f/(1.f+__expf(-v)); }

// ---------------- init: zero h(parity 0) and c ----------------
__global__ void init_kernel(){
    int i = blockIdx.x*blockDim.x + threadIdx.x;
    if (i < BB*HE){
        g_h[0][0][i]=0.f; g_h[1][0][i]=0.f;
        g_c[0][i]=0.f;    g_c[1][i]=0.f;
    }
}

// ---------------- encoder step: one time step, both directions ----------------
// grid (8 batch-tiles, 8 j-tiles, 2 dirs), 128 threads, 64x128 tile, 8x8 microtile, K=317
__global__ void __launch_bounds__(128) enc_step_kernel(
    const float* __restrict__ x,
    const float* __restrict__ Wih_f, const float* __restrict__ Whh_f, const float* __restrict__ b_f,
    const float* __restrict__ Wih_b, const float* __restrict__ Whh_b, const float* __restrict__ b_b,
    int t)
{
    const int b0  = blockIdx.x*64;
    const int j0  = blockIdx.y*32;
    const int dir = blockIdx.z;
    const float* Wih  = dir ? Wih_b : Wih_f;
    const float* Whh  = dir ? Whh_b : Whh_f;
    const float* bias = dir ? b_b   : b_f;
    const int tpos = dir ? (TT-1-t) : t;           // input time index == enc store position
    const float* hprev = g_h[dir][t&1];
    float* hnext = g_h[dir][(t+1)&1];
    float* cbuf  = g_c[dir];

    __shared__ float sA[8*68];    // [kk][m], pad 68
    __shared__ float sB[8*132];   // [kk][n], pad 132

    const int tid = threadIdx.x;
    const int tx = tid & 15;      // 16 col-groups of 8
    const int ty = tid >> 4;      // 8 row-groups of 8

    float acc[8][8] = {};

    // fetch assignment: A -> thread loads 4 k for row m; B -> 8 k for col n
    const int am  = tid >> 1;            // 0..63
    const int akb = (tid & 1) * 4;
    const int agb = b0 + am;
    const int bn  = tid;                 // 0..127 ; col n -> W row = (n&3)*HE + j0 + (n>>2)
    const int wrow = (bn & 3)*HE + j0 + (bn >> 2);
    const float* xrow   = x     + ((size_t)agb*TT + tpos)*PP;
    const float* hrow   = hprev + (size_t)agb*HE;
    const float* wihrow = Wih   + (size_t)wrow*PP;
    const float* whhrow = Whh   + (size_t)wrow*HE;

    float ra[4], rb[8];
    auto fetch = [&](int k0){
        #pragma unroll
        for (int i=0;i<4;i++){ int k=k0+akb+i;
            ra[i] = (k<PP) ? xrow[k] : ((k<PP+HE) ? hrow[k-PP] : 0.f); }
        #pragma unroll
        for (int i=0;i<8;i++){ int k=k0+i;
            rb[i] = (k<PP) ? wihrow[k] : ((k<PP+HE) ? whhrow[k-PP] : 0.f); }
    };

    const int NCH = (PP+HE+7)/8;   // 40
    fetch(0);
    for (int ch=0; ch<NCH; ch++){
        __syncthreads();
        #pragma unroll
        for (int i=0;i<4;i++) sA[(akb+i)*68 + am] = ra[i];
        #pragma unroll
        for (int i=0;i<8;i++) sB[i*132 + bn] = rb[i];
        __syncthreads();
        if (ch+1 < NCH) fetch((ch+1)*8);
        #pragma unroll
        for (int kk=0;kk<8;kk++){
            float4 a0 = *(const float4*)&sA[kk*68 + ty*8];
            float4 a1 = *(const float4*)&sA[kk*68 + ty*8 + 4];
            float4 bq0 = *(const float4*)&sB[kk*132 + tx*8];
            float4 bq1 = *(const float4*)&sB[kk*132 + tx*8 + 4];
            float a[8] = {a0.x,a0.y,a0.z,a0.w,a1.x,a1.y,a1.z,a1.w};
            float b[8] = {bq0.x,bq0.y,bq0.z,bq0.w,bq1.x,bq1.y,bq1.z,bq1.w};
            #pragma unroll
            for (int r=0;r<8;r++)
                #pragma unroll
                for (int i=0;i<8;i++) acc[r][i] = fmaf(a[r], b[i], acc[r][i]);
        }
    }

    // epilogue: fused LSTM cell. cols n=tx*8+i -> gate g=i&3, jj=tx*2+(i>>2)
    #pragma unroll
    for (int r=0;r<8;r++){
        const int gb = b0 + ty*8 + r;
        #pragma unroll
        for (int q=0;q<2;q++){
            const int j = j0 + tx*2 + q;
            const int o = q*4;
            float iv = sigmoidf_(acc[r][o+0] + bias[j]);
            float fv = sigmoidf_(acc[r][o+1] + bias[HE+j]);
            float gv = tanhf    (acc[r][o+2] + bias[2*HE+j]);
            float ov = sigmoidf_(acc[r][o+3] + bias[3*HE+j]);
            float cn = fv*cbuf[(size_t)gb*HE+j] + iv*gv;
            float hn = ov*tanhf(cn);
            cbuf [(size_t)gb*HE+j] = cn;
            hnext[(size_t)gb*HE+j] = hn;
            g_enc[((size_t)gb*TT + tpos)*512 + dir*HE + j] = hn;
        }
    }
}

// ---------------- encoderOut GEMM: (131072,512)@(512,1024) + split/softplus ----------------
// grid (8 n-tiles, 1024 m-tiles), 256 threads, 128x128 tile, 8x8 microtile
__global__ void __launch_bounds__(256) encout_kernel(
    const float* __restrict__ Wout, const float* __restrict__ bout,
    float* __restrict__ mu_out, float* __restrict__ lv_out)
{
    const int n0 = blockIdx.x*128, r0 = blockIdx.y*128;
    __shared__ float sA[8*132], sB[8*132];
    const int tid = threadIdx.x, tx = tid&15, ty = tid>>4;
    const int m = tid>>1, kb = (tid&1)*4;
    const float* arow = g_enc + (size_t)(r0+m)*512;
    const float* brow = Wout  + (size_t)(n0+m)*512;

    float acc[8][8] = {};
    float4 ra, rb;
    auto fetch = [&](int k0){
        ra = *(const float4*)&arow[k0+kb];
        rb = *(const float4*)&brow[k0+kb];
    };
    fetch(0);
    for (int ch=0; ch<64; ch++){
        __syncthreads();
        sA[(kb+0)*132+m]=ra.x; sA[(kb+1)*132+m]=ra.y; sA[(kb+2)*132+m]=ra.z; sA[(kb+3)*132+m]=ra.w;
        sB[(kb+0)*132+m]=rb.x; sB[(kb+1)*132+m]=rb.y; sB[(kb+2)*132+m]=rb.z; sB[(kb+3)*132+m]=rb.w;
        __syncthreads();
        if (ch<63) fetch((ch+1)*8);
        #pragma unroll
        for (int kk=0;kk<8;kk++){
            float4 a0 = *(const float4*)&sA[kk*132 + ty*8];
            float4 a1 = *(const float4*)&sA[kk*132 + ty*8 + 4];
            float4 b0 = *(const float4*)&sB[kk*132 + tx*8];
            float4 b1 = *(const float4*)&sB[kk*132 + tx*8 + 4];
            float a[8] = {a0.x,a0.y,a0.z,a0.w,a1.x,a1.y,a1.z,a1.w};
            float b[8] = {b0.x,b0.y,b0.z,b0.w,b1.x,b1.y,b1.z,b1.w};
            #pragma unroll
            for (int r=0;r<8;r++)
                #pragma unroll
                for (int i=0;i<8;i++) acc[r][i] = fmaf(a[r], b[i], acc[r][i]);
        }
    }
    #pragma unroll
    for (int ri=0;ri<8;ri++){
        const size_t r = r0 + ty*8 + ri;
        #pragma unroll
        for (int ci=0;ci<8;ci++){
            const int col = n0 + tx*8 + ci;
            float v = acc[ri][ci] + bout[col];
            if (col < LATD) mu_out[r*LATD + col] = v;
            else {
                float sp = (v > 20.f) ? v : log1pf(__expf(v));
                lv_out[r*LATD + (col-LATD)] = sp;
            }
        }
    }
}

// ---------------- z projection: z = (mu + eps*exp(2*lv)) @ Wz.T + bz ----------------
// grid (1024 m-tiles), 256 threads, 128x32 tile, K=512
__global__ void __launch_bounds__(256) zproj_kernel(
    const float* __restrict__ mu, const float* __restrict__ lv, const float* __restrict__ eps,
    const float* __restrict__ Wz, const float* __restrict__ bz, float* __restrict__ zout)
{
    const int r0 = blockIdx.x*128;
    __shared__ float sA[8*132], sB[8*33];
    const int tid = threadIdx.x, tx = tid&15, ty = tid>>4;
    const int m = tid>>1, kb = (tid&1)*4;
    const size_t rr = (size_t)r0 + m;
    const int bidx = (int)(rr >> 8);
    const float* murow  = mu  + rr*LATD;
    const float* lvrow  = lv  + rr*LATD;
    const float* epsrow = eps + (size_t)bidx*LATD;
    const int bnn = tid>>3, bkk = tid&7;   // 32 cols x 8 kk

    float acc[8][2] = {};
    float ra[4], rb;
    auto fetch = [&](int k0){
        float4 m4 = *(const float4*)&murow[k0+kb];
        float4 l4 = *(const float4*)&lvrow[k0+kb];
        float4 e4 = *(const float4*)&epsrow[k0+kb];
        ra[0] = m4.x + e4.x*__expf(2.f*l4.x);
        ra[1] = m4.y + e4.y*__expf(2.f*l4.y);
        ra[2] = m4.z + e4.z*__expf(2.f*l4.z);
        ra[3] = m4.w + e4.w*__expf(2.f*l4.w);
        rb = Wz[(size_t)bnn*LATD + k0 + bkk];
    };
    fetch(0);
    for (int ch=0; ch<64; ch++){
        __syncthreads();
        #pragma unroll
        for (int i=0;i<4;i++) sA[(kb+i)*132+m] = ra[i];
        sB[bkk*33 + bnn] = rb;
        __syncthreads();
        if (ch<63) fetch((ch+1)*8);
        #pragma unroll
        for (int kk=0;kk<8;kk++){
            float4 a0 = *(const float4*)&sA[kk*132 + ty*8];
            float4 a1 = *(const float4*)&sA[kk*132 + ty*8 + 4];
            float a[8] = {a0.x,a0.y,a0.z,a0.w,a1.x,a1.y,a1.z,a1.w};
            float bv0 = sB[kk*33 + tx*2 + 0];
            float bv1 = sB[kk*33 + tx*2 + 1];
            #pragma unroll
            for (int r=0;r<8;r++){
                acc[r][0] = fmaf(a[r], bv0, acc[r][0]);
                acc[r][1] = fmaf(a[r], bv1, acc[r][1]);
            }
        }
    }
    #pragma unroll
    for (int ri=0;ri<8;ri++){
        const size_t r = r0 + ty*8 + ri;
        #pragma unroll
        for (int ci=0;ci<2;ci++){
            const int col = tx*2 + ci;
            zout[r*DECD + col] = acc[ri][ci] + bz[col];
        }
    }
}

// ---------------- conductor LSTM over z[:, :16, :] ----------------
// grid 32 blocks x 16 batch rows, 256 threads; per-row recurrence independent
__global__ void __launch_bounds__(256) conductor_kernel(
    const float* __restrict__ zout, const float* __restrict__ Wih,
    const float* __restrict__ Whh, const float* __restrict__ bias)
{
    __shared__ float sWi[128*33], sWh[128*33], sb[128];
    __shared__ float sh[16*33], sc[16*33], sz[16*33];
    const int tid = threadIdx.x;
    const int b0 = blockIdx.x*16;
    for (int i=tid; i<128*32; i+=256){ int cc=i>>5, k=i&31; sWi[cc*33+k]=Wih[i]; sWh[cc*33+k]=Whh[i]; }
    if (tid < 128) sb[tid] = bias[tid];
    for (int i=tid; i<16*32; i+=256){ int mm=i>>5, k=i&31; sh[mm*33+k]=0.f; sc[mm*33+k]=0.f; }
    __syncthreads();

    const int j  = tid & 31;
    const int m0 = tid >> 5;     // 0..7, handles rows m0 and m0+8
    for (int t=0; t<TBAR; t++){
        for (int i=tid; i<16*32; i+=256){
            int mm=i>>5, k=i&31;
            sz[mm*33+k] = zout[((size_t)(b0+mm)*TT + t)*DECD + k];
        }
        __syncthreads();
        float hn[2], cn[2];
        #pragma unroll
        for (int p=0;p<2;p++){
            const int mm = m0 + p*8;
            float a0=sb[j], a1=sb[32+j], a2=sb[64+j], a3=sb[96+j];
            #pragma unroll
            for (int k=0;k<32;k++){
                float zv = sz[mm*33+k], hv = sh[mm*33+k];
                a0 += zv*sWi[( j      )*33+k] + hv*sWh[( j      )*33+k];
                a1 += zv*sWi[(32+j)*33+k]     + hv*sWh[(32+j)*33+k];
                a2 += zv*sWi[(64+j)*33+k]     + hv*sWh[(64+j)*33+k];
                a3 += zv*sWi[(96+j)*33+k]     + hv*sWh[(96+j)*33+k];
            }
            float iv=sigmoidf_(a0), fv=sigmoidf_(a1), gv=tanhf(a2), ov=sigmoidf_(a3);
            cn[p] = fv*sc[mm*33+j] + iv*gv;
            hn[p] = ov*tanhf(cn[p]);
        }
        __syncthreads();
        #pragma unroll
        for (int p=0;p<2;p++){
            const int mm = m0 + p*8;
            sh[mm*33+j]=hn[p]; sc[mm*33+j]=cn[p];
            g_emb[((size_t)(b0+mm)*TBAR + t)*DECD + j] = hn[p];
        }
        __syncthreads();
    }
}

// ---------------- decoder LSTM + output linear + softmax ----------------
// warp per (batch,bar) row; 1024 blocks x 8 warps; dynamic smem 73728B
__global__ void __launch_bounds__(256) decoder_kernel(
    const float* __restrict__ x, const float* __restrict__ h0in, const float* __restrict__ c0in,
    const float* __restrict__ Wih, const float* __restrict__ Whh, const float* __restrict__ bias,
    const float* __restrict__ Wlin, const float* __restrict__ blin,
    float* __restrict__ notes)
{
    extern __shared__ float sm[];
    float* sWi = sm;                 // 128*93
    float* sWh = sWi + 128*93;       // 128*33 (padded)
    float* sb  = sWh + 128*33;       // 128
    float* sWl = sb + 128;           // 64*33 (padded, rows>=61 zero)
    float* sbl = sWl + 64*33;        // 64
    const int tid = threadIdx.x;
    for (int i=tid; i<128*93; i+=256) sWi[i] = Wih[i];
    for (int i=tid; i<128*32; i+=256){ int cc=i>>5, k=i&31; sWh[cc*33+k] = Whh[i]; }
    if (tid < 128) sb[tid] = bias[tid];
    for (int i=tid; i<64*32; i+=256){ int cc=i>>5, k=i&31; sWl[cc*33+k] = (cc<PP) ? Wlin[i] : 0.f; }
    if (tid < 64) sbl[tid] = (tid<PP) ? blin[tid] : 0.f;
    __syncthreads();

    const int w = tid>>5, lane = tid&31;
    const int row  = blockIdx.x*8 + w;       // 0..8191  (= b*16 + bar)
    const int bidx = row>>4, bar = row&15;
    float h = h0in[((size_t)bar*BB + bidx)*DECD + lane];
    float c = c0in[((size_t)bar*BB + bidx)*DECD + lane];
    const float emb = g_emb[(size_t)row*DECD + lane];
    const unsigned FULL = 0xffffffffu;
    const int c0_=lane, c1_=32+lane, c2_=64+lane, c3_=96+lane;

    for (int n=0;n<16;n++){
        const int time = bar*16 + n;
        float t0 = 0.f, t1 = 0.f;
        if (time > 0){
            const float* xr = x + ((size_t)bidx*TT + time-1)*PP;
            t0 = xr[lane];
            if (lane < 29) t1 = xr[32+lane];
        }
        float a0=sb[c0_], a1=sb[c1_], a2=sb[c2_], a3=sb[c3_];
        #pragma unroll
        for (int k=0;k<32;k++){
            float av = __shfl_sync(FULL, emb, k);
            a0 = fmaf(av, sWi[c0_*93+k], a0); a1 = fmaf(av, sWi[c1_*93+k], a1);
            a2 = fmaf(av, sWi[c2_*93+k], a2); a3 = fmaf(av, sWi[c3_*93+k], a3);
        }
        #pragma unroll
        for (int k=0;k<32;k++){
            float av = __shfl_sync(FULL, t0, k); const int kk=32+k;
            a0 = fmaf(av, sWi[c0_*93+kk], a0); a1 = fmaf(av, sWi[c1_*93+kk], a1);
            a2 = fmaf(av, sWi[c2_*93+kk], a2); a3 = fmaf(av, sWi[c3_*93+kk], a3);
        }
        #pragma unroll
        for (int k=0;k<29;k++){
            float av = __shfl_sync(FULL, t1, k); const int kk=64+k;
            a0 = fmaf(av, sWi[c0_*93+kk], a0); a1 = fmaf(av, sWi[c1_*93+kk], a1);
            a2 = fmaf(av, sWi[c2_*93+kk], a2); a3 = fmaf(av, sWi[c3_*93+kk], a3);
        }
        #pragma unroll
        for (int k=0;k<32;k++){
            float av = __shfl_sync(FULL, h, k);
            a0 = fmaf(av, sWh[c0_*33+k], a0); a1 = fmaf(av, sWh[c1_*33+k], a1);
            a2 = fmaf(av, sWh[c2_*33+k], a2); a3 = fmaf(av, sWh[c3_*33+k], a3);
        }
        float iv=sigmoidf_(a0), fv=sigmoidf_(a1), gv=tanhf(a2), ov=sigmoidf_(a3);
        c = fv*c + iv*gv;
        h = ov*tanhf(c);

        // output linear: lanes hold logits lane and 32+lane (valid < 61)
        float l0 = sbl[lane], l1 = sbl[32+lane];
        #pragma unroll
        for (int k=0;k<32;k++){
            float hv = __shfl_sync(FULL, h, k);
            l0 = fmaf(hv, sWl[lane*33+k], l0);
            l1 = fmaf(hv, sWl[(32+lane)*33+k], l1);
        }
        float l1m = (lane < 29) ? l1 : -1e30f;
        float mx = fmaxf(l0, l1m);
        #pragma unroll
        for (int off=16; off; off>>=1) mx = fmaxf(mx, __shfl_xor_sync(FULL, mx, off));
        float e0 = __expf(l0 - mx);
        float e1 = (lane < 29) ? __expf(l1 - mx) : 0.f;
        float s = e0 + e1;
        #pragma unroll
        for (int off=16; off; off>>=1) s += __shfl_xor_sync(FULL, s, off);
        const float inv = 1.f/s;
        float* nr = notes + ((size_t)bidx*TT + time)*PP;
        nr[lane] = e0*inv;
        if (lane < 29) nr[32+lane] = e1*inv;
    }
}

// ---------------- launch ----------------
extern "C" void kernel_launch(void* const* d_in, const int* in_sizes, int n_in,
                              void* d_out, int out_size)
{
    const float* x        = (const float*)d_in[0];
    const float* eps      = (const float*)d_in[1];
    const float* dec_h0   = (const float*)d_in[2];
    const float* dec_c0   = (const float*)d_in[3];
    const float* eWih_f   = (const float*)d_in[4];
    const float* eWhh_f   = (const float*)d_in[5];
    const float* eb_f     = (const float*)d_in[6];
    const float* eWih_b   = (const float*)d_in[7];
    const float* eWhh_b   = (const float*)d_in[8];
    const float* eb_b     = (const float*)d_in[9];
    const float* Wout     = (const float*)d_in[10];
    const float* bout     = (const float*)d_in[11];
    const float* Wz       = (const float*)d_in[12];
    const float* bz       = (const float*)d_in[13];
    const float* conWih   = (const float*)d_in[14];
    const float* conWhh   = (const float*)d_in[15];
    const float* conb     = (const float*)d_in[16];
    const float* dWih     = (const float*)d_in[17];
    const float* dWhh     = (const float*)d_in[18];
    const float* db       = (const float*)d_in[19];
    const float* Wlin     = (const float*)d_in[20];
    const float* blin     = (const float*)d_in[21];

    float* out   = (float*)d_out;
    float* notes = out;                                   // (B,T,P)   7,995,392
    float* zout  = out + (size_t)NROWS*PP;                // (B,T,DEC) 4,194,304
    float* muo   = zout + (size_t)NROWS*DECD;             // (B,T,LAT)
    float* lvo   = muo  + (size_t)NROWS*LATD;             // (B,T,LAT)

    init_kernel<<<(BB*HE+255)/256, 256>>>();

    for (int t=0; t<TT; t++)
        enc_step_kernel<<<dim3(8,8,2), 128>>>(x, eWih_f, eWhh_f, eb_f,
                                              eWih_b, eWhh_b, eb_b, t);

    encout_kernel<<<dim3(8, NROWS/128), 256>>>(Wout, bout, muo, lvo);

    zproj_kernel<<<NROWS/128, 256>>>(muo, lvo, eps, Wz, bz, zout);

    conductor_kernel<<<BB/16, 256>>>(zout, conWih, conWhh, conb);

    cudaFuncSetAttribute(decoder_kernel, cudaFuncAttributeMaxDynamicSharedMemorySize, 73728);
    decoder_kernel<<<(BB*TBAR)/8, 256, 73728>>>(x, dec_h0, dec_c0,
                                                dWih, dWhh, db, Wlin, blin, notes);
}

// round 2
// speedup vs baseline: 1.8141x; 1.8141x over previous
#include <cuda_runtime.h>
#include <math.h>
#include <stdint.h>

#define BB   512
#define TT   256
#define PP   61
#define HE   256
#define LATD 512
#define DECD 32
#define TBAR 16
#define NROWS (BB*TT)   // 131072
#define NBLK 128        // persistent encoder grid (<148 SMs -> co-resident)

// ---------------- scratch (device globals; no allocation allowed) ----------------
__device__ float g_enc[(size_t)NROWS*512];     // (B*T, 2H) encoder outputs
__device__ float g_h[2][2][BB*HE];             // [dir][parity][B*H] hidden double-buffer
__device__ float g_emb[(size_t)BB*TBAR*DECD];  // conductor embeddings (row = b*16+bar)

// grid barrier state (sense-reversing; self-resetting across graph replays)
__device__ unsigned g_count = 0;
__device__ volatile unsigned g_sense = 0;

typedef unsigned long long u64;

__device__ __forceinline__ float sigmoidf_(float v){ return 1.f/(1.f+__expf(-v)); }

__device__ __forceinline__ u64 pk2(float lo, float hi){
    u64 r; asm("mov.b64 %0, {%1,%2};" : "=l"(r) : "f"(lo), "f"(hi)); return r;
}
__device__ __forceinline__ void upk2(u64 v, float &lo, float &hi){
    asm("mov.b64 {%0,%1}, %2;" : "=f"(lo), "=f"(hi) : "l"(v));
}
__device__ __forceinline__ void ffma2(u64 &d, u64 a, u64 b){
    asm("fma.rn.f32x2 %0, %1, %2, %0;" : "+l"(d) : "l"(a), "l"(b));
}

// ---------------- persistent bidirectional encoder ----------------
// 128 blocks x 256 threads. block: dir(1b) | btile(3b) | ntile(3b)
// tile 64 rows x 128 gate-cols, K = 317 (h 256 | x 61, padded to 320)
__global__ void __launch_bounds__(256, 1) enc_persist_kernel(
    const float* __restrict__ x,
    const float* __restrict__ Wih_f, const float* __restrict__ Whh_f, const float* __restrict__ b_f,
    const float* __restrict__ Wih_b, const float* __restrict__ Whh_b, const float* __restrict__ b_b)
{
    const int bid = blockIdx.x;
    const int dir = bid >> 6;
    const int bt  = (bid >> 3) & 7;
    const int nt  = bid & 7;
    const int b0 = bt*64, j0 = nt*32;
    const float* Wih  = dir ? Wih_b : Wih_f;
    const float* Whh  = dir ? Whh_b : Whh_f;
    const float* bias = dir ? b_b   : b_f;

    __shared__ float sA[8][68];
    __shared__ float sB[8][132];
    __shared__ unsigned s_sense;

    const int tid = threadIdx.x;
    if (tid == 0) s_sense = g_sense;   // read before any barrier can complete

    // zero-init owned slice of h parity 0
    for (int i = tid; i < 64*32; i += 256){
        int r = i >> 5, j = j0 + (i & 31);
        g_h[dir][0][(size_t)(b0+r)*HE + j] = 0.f;
    }

    // ---- grid barrier helper (inline each use) ----
#define GRID_BAR() do {                                            \
        __threadfence();                                           \
        __syncthreads();                                           \
        if (tid == 0){                                             \
            unsigned my = s_sense;                                 \
            unsigned old = atomicAdd(&g_count, 1u);                \
            if (old == NBLK-1){                                    \
                g_count = 0;                                       \
                __threadfence();                                   \
                g_sense = my ^ 1u;                                 \
            } else {                                               \
                while (g_sense == my) __nanosleep(64);             \
            }                                                      \
            s_sense = my ^ 1u;                                     \
        }                                                          \
        __syncthreads();                                           \
    } while(0)

    GRID_BAR();   // h init visible everywhere

    const int tx = tid & 31;      // j within tile; cols c = tx*4..+3 = gates i,f,g,o of j
    const int ty = tid >> 5;      // row group: rows ty*8 .. ty*8+7
    const int jj = j0 + tx;

    // fetch assignment
    const int am  = tid >> 2;            // A row 0..63
    const int akb = (tid & 3) * 2;       // 2 consecutive k
    const int bn  = tid >> 1;            // B col 0..127
    const int bkb = (tid & 1) * 4;       // 4 consecutive k
    const int wg  = bn & 3, wj = j0 + (bn >> 2);
    const float* whhrow = Whh + (size_t)(wg*HE + wj)*HE;
    const float* wihrow = Wih + (size_t)(wg*HE + wj)*PP;

    // per-thread persistent state
    float creg[8];
    #pragma unroll
    for (int r=0;r<8;r++) creg[r] = 0.f;
    float biasv[4];
    #pragma unroll
    for (int g=0; g<4; g++) biasv[g] = bias[g*HE + jj];

    float ra[2], rb[4];

    for (int t=0; t<TT; t++){
        const int tpos = dir ? (TT-1-t) : t;
        const float* hprev = g_h[dir][t&1];
        float* hnext = g_h[dir][(t+1)&1];
        const float* hrow = hprev + (size_t)(b0+am)*HE;
        const float* xrow = x + ((size_t)(b0+am)*TT + tpos)*PP;

        u64 acc[4][4];
        #pragma unroll
        for (int p=0;p<4;p++)
            #pragma unroll
            for (int c=0;c<4;c++) acc[p][c] = 0ull;

        auto fetch = [&](int k0){
            if (k0 < HE){
                float2 v = __ldcg((const float2*)(hrow + k0 + akb));
                ra[0]=v.x; ra[1]=v.y;
                float4 w = __ldg((const float4*)(whhrow + k0 + bkb));
                rb[0]=w.x; rb[1]=w.y; rb[2]=w.z; rb[3]=w.w;
            } else {
                #pragma unroll
                for (int i=0;i<2;i++){ int ko = k0 + akb + i - HE;
                    ra[i] = (ko < PP) ? __ldg(xrow + ko) : 0.f; }
                #pragma unroll
                for (int i=0;i<4;i++){ int ko = k0 + bkb + i - HE;
                    rb[i] = (ko < PP) ? __ldg(wihrow + ko) : 0.f; }
            }
        };

        fetch(0);
        for (int ch=0; ch<40; ch++){
            __syncthreads();
            #pragma unroll
            for (int i=0;i<2;i++) sA[akb+i][am] = ra[i];
            #pragma unroll
            for (int i=0;i<4;i++) sB[bkb+i][bn] = rb[i];
            __syncthreads();
            if (ch+1 < 40) fetch((ch+1)*8);
            #pragma unroll
            for (int kk=0;kk<8;kk++){
                const float4 a0 = *(const float4*)&sA[kk][ty*8];
                const float4 a1 = *(const float4*)&sA[kk][ty*8+4];
                const float4 bq = *(const float4*)&sB[kk][tx*4];
                u64 ap[4] = { pk2(a0.x,a0.y), pk2(a0.z,a0.w),
                              pk2(a1.x,a1.y), pk2(a1.z,a1.w) };
                u64 bd[4] = { pk2(bq.x,bq.x), pk2(bq.y,bq.y),
                              pk2(bq.z,bq.z), pk2(bq.w,bq.w) };
                #pragma unroll
                for (int p=0;p<4;p++)
                    #pragma unroll
                    for (int c=0;c<4;c++) ffma2(acc[p][c], ap[p], bd[c]);
            }
        }

        // ---- fused LSTM cell epilogue ----
        #pragma unroll
        for (int p=0;p<4;p++){
            float gi[2], gf[2], gg[2], go[2];
            upk2(acc[p][0], gi[0], gi[1]);
            upk2(acc[p][1], gf[0], gf[1]);
            upk2(acc[p][2], gg[0], gg[1]);
            upk2(acc[p][3], go[0], go[1]);
            #pragma unroll
            for (int hh=0; hh<2; hh++){
                const int rloc = 2*p + hh;
                const int gb = b0 + ty*8 + rloc;
                float iv = sigmoidf_(gi[hh] + biasv[0]);
                float fv = sigmoidf_(gf[hh] + biasv[1]);
                float gv = tanhf    (gg[hh] + biasv[2]);
                float ov = sigmoidf_(go[hh] + biasv[3]);
                float cn = fv*creg[rloc] + iv*gv;
                float hn = ov*tanhf(cn);
                creg[rloc] = cn;
                hnext[(size_t)gb*HE + jj] = hn;
                g_enc[((size_t)gb*TT + tpos)*512 + dir*HE + jj] = hn;
            }
        }
        GRID_BAR();
    }
#undef GRID_BAR
}

// ---------------- encoderOut GEMM: (131072,512)@(512,1024) + split/softplus ----------------
// grid (8 n-tiles, 1024 m-tiles), 256 threads, 128x128 tile, 8x8 microtile, f32x2
__global__ void __launch_bounds__(256) encout_kernel(
    const float* __restrict__ Wout, const float* __restrict__ bout,
    float* __restrict__ mu_out, float* __restrict__ lv_out)
{
    const int n0 = blockIdx.x*128, r0 = blockIdx.y*128;
    __shared__ float sA[8*132], sB[8*132];
    const int tid = threadIdx.x, tx = tid&15, ty = tid>>4;
    const int m = tid>>1, kb = (tid&1)*4;
    const float* arow = g_enc + (size_t)(r0+m)*512;
    const float* brow = Wout  + (size_t)(n0+m)*512;

    u64 acc[4][8];
    #pragma unroll
    for (int p=0;p<4;p++)
        #pragma unroll
        for (int c=0;c<8;c++) acc[p][c] = 0ull;

    float4 ra, rb;
    auto fetch = [&](int k0){
        ra = *(const float4*)&arow[k0+kb];
        rb = *(const float4*)&brow[k0+kb];
    };
    fetch(0);
    for (int ch=0; ch<64; ch++){
        __syncthreads();
        sA[(kb+0)*132+m]=ra.x; sA[(kb+1)*132+m]=ra.y; sA[(kb+2)*132+m]=ra.z; sA[(kb+3)*132+m]=ra.w;
        sB[(kb+0)*132+m]=rb.x; sB[(kb+1)*132+m]=rb.y; sB[(kb+2)*132+m]=rb.z; sB[(kb+3)*132+m]=rb.w;
        __syncthreads();
        if (ch<63) fetch((ch+1)*8);
        #pragma unroll
        for (int kk=0;kk<8;kk++){
            float4 a0 = *(const float4*)&sA[kk*132 + ty*8];
            float4 a1 = *(const float4*)&sA[kk*132 + ty*8 + 4];
            float4 b0 = *(const float4*)&sB[kk*132 + tx*8];
            float4 b1 = *(const float4*)&sB[kk*132 + tx*8 + 4];
            u64 ap[4] = { pk2(a0.x,a0.y), pk2(a0.z,a0.w),
                          pk2(a1.x,a1.y), pk2(a1.z,a1.w) };
            u64 bd[8] = { pk2(b0.x,b0.x), pk2(b0.y,b0.y), pk2(b0.z,b0.z), pk2(b0.w,b0.w),
                          pk2(b1.x,b1.x), pk2(b1.y,b1.y), pk2(b1.z,b1.z), pk2(b1.w,b1.w) };
            #pragma unroll
            for (int p=0;p<4;p++)
                #pragma unroll
                for (int c=0;c<8;c++) ffma2(acc[p][c], ap[p], bd[c]);
        }
    }
    #pragma unroll
    for (int p=0;p<4;p++){
        #pragma unroll
        for (int ci=0;ci<8;ci++){
            float lo, hi;
            upk2(acc[p][ci], lo, hi);
            const int col = n0 + tx*8 + ci;
            const float bv = bout[col];
            #pragma unroll
            for (int hh=0;hh<2;hh++){
                const size_t r = r0 + ty*8 + 2*p + hh;
                float v = (hh ? hi : lo) + bv;
                if (col < LATD) mu_out[r*LATD + col] = v;
                else {
                    float sp = (v > 20.f) ? v : log1pf(__expf(v));
                    lv_out[r*LATD + (col-LATD)] = sp;
                }
            }
        }
    }
}

// ---------------- z projection: z = (mu + eps*exp(2*lv)) @ Wz.T + bz ----------------
__global__ void __launch_bounds__(256) zproj_kernel(
    const float* __restrict__ mu, const float* __restrict__ lv, const float* __restrict__ eps,
    const float* __restrict__ Wz, const float* __restrict__ bz, float* __restrict__ zout)
{
    const int r0 = blockIdx.x*128;
    __shared__ float sA[8*132], sB[8*33];
    const int tid = threadIdx.x, tx = tid&15, ty = tid>>4;
    const int m = tid>>1, kb = (tid&1)*4;
    const size_t rr = (size_t)r0 + m;
    const int bidx = (int)(rr >> 8);
    const float* murow  = mu  + rr*LATD;
    const float* lvrow  = lv  + rr*LATD;
    const float* epsrow = eps + (size_t)bidx*LATD;
    const int bnn = tid>>3, bkk = tid&7;

    float acc[8][2] = {};
    float ra[4], rb;
    auto fetch = [&](int k0){
        float4 m4 = *(const float4*)&murow[k0+kb];
        float4 l4 = *(const float4*)&lvrow[k0+kb];
        float4 e4 = *(const float4*)&epsrow[k0+kb];
        ra[0] = m4.x + e4.x*__expf(2.f*l4.x);
        ra[1] = m4.y + e4.y*__expf(2.f*l4.y);
        ra[2] = m4.z + e4.z*__expf(2.f*l4.z);
        ra[3] = m4.w + e4.w*__expf(2.f*l4.w);
        rb = Wz[(size_t)bnn*LATD + k0 + bkk];
    };
    fetch(0);
    for (int ch=0; ch<64; ch++){
        __syncthreads();
        #pragma unroll
        for (int i=0;i<4;i++) sA[(kb+i)*132+m] = ra[i];
        sB[bkk*33 + bnn] = rb;
        __syncthreads();
        if (ch<63) fetch((ch+1)*8);
        #pragma unroll
        for (int kk=0;kk<8;kk++){
            float4 a0 = *(const float4*)&sA[kk*132 + ty*8];
            float4 a1 = *(const float4*)&sA[kk*132 + ty*8 + 4];
            float a[8] = {a0.x,a0.y,a0.z,a0.w,a1.x,a1.y,a1.z,a1.w};
            float bv0 = sB[kk*33 + tx*2 + 0];
            float bv1 = sB[kk*33 + tx*2 + 1];
            #pragma unroll
            for (int r=0;r<8;r++){
                acc[r][0] = fmaf(a[r], bv0, acc[r][0]);
                acc[r][1] = fmaf(a[r], bv1, acc[r][1]);
            }
        }
    }
    #pragma unroll
    for (int ri=0;ri<8;ri++){
        const size_t r = r0 + ty*8 + ri;
        #pragma unroll
        for (int ci=0;ci<2;ci++){
            const int col = tx*2 + ci;
            zout[r*DECD + col] = acc[ri][ci] + bz[col];
        }
    }
}

// ---------------- conductor LSTM over z[:, :16, :] ----------------
__global__ void __launch_bounds__(256) conductor_kernel(
    const float* __restrict__ zout, const float* __restrict__ Wih,
    const float* __restrict__ Whh, const float* __restrict__ bias)
{
    __shared__ float sWi[128*33], sWh[128*33], sb[128];
    __shared__ float sh[16*33], sc[16*33], sz[16*33];
    const int tid = threadIdx.x;
    const int b0 = blockIdx.x*16;
    for (int i=tid; i<128*32; i+=256){ int cc=i>>5, k=i&31; sWi[cc*33+k]=Wih[i]; sWh[cc*33+k]=Whh[i]; }
    if (tid < 128) sb[tid] = bias[tid];
    for (int i=tid; i<16*32; i+=256){ int mm=i>>5, k=i&31; sh[mm*33+k]=0.f; sc[mm*33+k]=0.f; }
    __syncthreads();

    const int j  = tid & 31;
    const int m0 = tid >> 5;
    for (int t=0; t<TBAR; t++){
        for (int i=tid; i<16*32; i+=256){
            int mm=i>>5, k=i&31;
            sz[mm*33+k] = zout[((size_t)(b0+mm)*TT + t)*DECD + k];
        }
        __syncthreads();
        float hn[2], cn[2];
        #pragma unroll
        for (int p=0;p<2;p++){
            const int mm = m0 + p*8;
            float a0=sb[j], a1=sb[32+j], a2=sb[64+j], a3=sb[96+j];
            #pragma unroll
            for (int k=0;k<32;k++){
                float zv = sz[mm*33+k], hv = sh[mm*33+k];
                a0 += zv*sWi[( j      )*33+k] + hv*sWh[( j      )*33+k];
                a1 += zv*sWi[(32+j)*33+k]     + hv*sWh[(32+j)*33+k];
                a2 += zv*sWi[(64+j)*33+k]     + hv*sWh[(64+j)*33+k];
                a3 += zv*sWi[(96+j)*33+k]     + hv*sWh[(96+j)*33+k];
            }
            float iv=sigmoidf_(a0), fv=sigmoidf_(a1), gv=tanhf(a2), ov=sigmoidf_(a3);
            cn[p] = fv*sc[mm*33+j] + iv*gv;
            hn[p] = ov*tanhf(cn[p]);
        }
        __syncthreads();
        #pragma unroll
        for (int p=0;p<2;p++){
            const int mm = m0 + p*8;
            sh[mm*33+j]=hn[p]; sc[mm*33+j]=cn[p];
            g_emb[((size_t)(b0+mm)*TBAR + t)*DECD + j] = hn[p];
        }
        __syncthreads();
    }
}

// ---------------- decoder LSTM + output linear + softmax ----------------
__global__ void __launch_bounds__(256) decoder_kernel(
    const float* __restrict__ x, const float* __restrict__ h0in, const float* __restrict__ c0in,
    const float* __restrict__ Wih, const float* __restrict__ Whh, const float* __restrict__ bias,
    const float* __restrict__ Wlin, const float* __restrict__ blin,
    float* __restrict__ notes)
{
    extern __shared__ float sm[];
    float* sWi = sm;                 // 128*93
    float* sWh = sWi + 128*93;       // 128*33 (padded)
    float* sb  = sWh + 128*33;       // 128
    float* sWl = sb + 128;           // 64*33 (padded, rows>=61 zero)
    float* sbl = sWl + 64*33;        // 64
    const int tid = threadIdx.x;
    for (int i=tid; i<128*93; i+=256) sWi[i] = Wih[i];
    for (int i=tid; i<128*32; i+=256){ int cc=i>>5, k=i&31; sWh[cc*33+k] = Whh[i]; }
    if (tid < 128) sb[tid] = bias[tid];
    for (int i=tid; i<64*32; i+=256){ int cc=i>>5, k=i&31; sWl[cc*33+k] = (cc<PP) ? Wlin[i] : 0.f; }
    if (tid < 64) sbl[tid] = (tid<PP) ? blin[tid] : 0.f;
    __syncthreads();

    const int w = tid>>5, lane = tid&31;
    const int row  = blockIdx.x*8 + w;
    const int bidx = row>>4, bar = row&15;
    float h = h0in[((size_t)bar*BB + bidx)*DECD + lane];
    float c = c0in[((size_t)bar*BB + bidx)*DECD + lane];
    const float emb = g_emb[(size_t)row*DECD + lane];
    const unsigned FULL = 0xffffffffu;
    const int c0_=lane, c1_=32+lane, c2_=64+lane, c3_=96+lane;

    for (int n=0;n<16;n++){
        const int time = bar*16 + n;
        float t0 = 0.f, t1 = 0.f;
        if (time > 0){
            const float* xr = x + ((size_t)bidx*TT + time-1)*PP;
            t0 = xr[lane];
            if (lane < 29) t1 = xr[32+lane];
        }
        float a0=sb[c0_], a1=sb[c1_], a2=sb[c2_], a3=sb[c3_];
        #pragma unroll
        for (int k=0;k<32;k++){
            float av = __shfl_sync(FULL, emb, k);
            a0 = fmaf(av, sWi[c0_*93+k], a0); a1 = fmaf(av, sWi[c1_*93+k], a1);
            a2 = fmaf(av, sWi[c2_*93+k], a2); a3 = fmaf(av, sWi[c3_*93+k], a3);
        }
        #pragma unroll
        for (int k=0;k<32;k++){
            float av = __shfl_sync(FULL, t0, k); const int kk=32+k;
            a0 = fmaf(av, sWi[c0_*93+kk], a0); a1 = fmaf(av, sWi[c1_*93+kk], a1);
            a2 = fmaf(av, sWi[c2_*93+kk], a2); a3 = fmaf(av, sWi[c3_*93+kk], a3);
        }
        #pragma unroll
        for (int k=0;k<29;k++){
            float av = __shfl_sync(FULL, t1, k); const int kk=64+k;
            a0 = fmaf(av, sWi[c0_*93+kk], a0); a1 = fmaf(av, sWi[c1_*93+kk], a1);
            a2 = fmaf(av, sWi[c2_*93+kk], a2); a3 = fmaf(av, sWi[c3_*93+kk], a3);
        }
        #pragma unroll
        for (int k=0;k<32;k++){
            float av = __shfl_sync(FULL, h, k);
            a0 = fmaf(av, sWh[c0_*33+k], a0); a1 = fmaf(av, sWh[c1_*33+k], a1);
            a2 = fmaf(av, sWh[c2_*33+k], a2); a3 = fmaf(av, sWh[c3_*33+k], a3);
        }
        float iv=sigmoidf_(a0), fv=sigmoidf_(a1), gv=tanhf(a2), ov=sigmoidf_(a3);
        c = fv*c + iv*gv;
        h = ov*tanhf(c);

        float l0 = sbl[lane], l1 = sbl[32+lane];
        #pragma unroll
        for (int k=0;k<32;k++){
            float hv = __shfl_sync(FULL, h, k);
            l0 = fmaf(hv, sWl[lane*33+k], l0);
            l1 = fmaf(hv, sWl[(32+lane)*33+k], l1);
        }
        float l1m = (lane < 29) ? l1 : -1e30f;
        float mx = fmaxf(l0, l1m);
        #pragma unroll
        for (int off=16; off; off>>=1) mx = fmaxf(mx, __shfl_xor_sync(FULL, mx, off));
        float e0 = __expf(l0 - mx);
        float e1 = (lane < 29) ? __expf(l1 - mx) : 0.f;
        float s = e0 + e1;
        #pragma unroll
        for (int off=16; off; off>>=1) s += __shfl_xor_sync(FULL, s, off);
        const float inv = 1.f/s;
        float* nr = notes + ((size_t)bidx*TT + time)*PP;
        nr[lane] = e0*inv;
        if (lane < 29) nr[32+lane] = e1*inv;
    }
}

// ---------------- launch ----------------
extern "C" void kernel_launch(void* const* d_in, const int* in_sizes, int n_in,
                              void* d_out, int out_size)
{
    const float* x        = (const float*)d_in[0];
    const float* eps      = (const float*)d_in[1];
    const float* dec_h0   = (const float*)d_in[2];
    const float* dec_c0   = (const float*)d_in[3];
    const float* eWih_f   = (const float*)d_in[4];
    const float* eWhh_f   = (const float*)d_in[5];
    const float* eb_f     = (const float*)d_in[6];
    const float* eWih_b   = (const float*)d_in[7];
    const float* eWhh_b   = (const float*)d_in[8];
    const float* eb_b     = (const float*)d_in[9];
    const float* Wout     = (const float*)d_in[10];
    const float* bout     = (const float*)d_in[11];
    const float* Wz       = (const float*)d_in[12];
    const float* bz       = (const float*)d_in[13];
    const float* conWih   = (const float*)d_in[14];
    const float* conWhh   = (const float*)d_in[15];
    const float* conb     = (const float*)d_in[16];
    const float* dWih     = (const float*)d_in[17];
    const float* dWhh     = (const float*)d_in[18];
    const float* db       = (const float*)d_in[19];
    const float* Wlin     = (const float*)d_in[20];
    const float* blin     = (const float*)d_in[21];

    float* out   = (float*)d_out;
    float* notes = out;                                   // (B,T,P)
    float* zout  = out + (size_t)NROWS*PP;                // (B,T,DEC)
    float* muo   = zout + (size_t)NROWS*DECD;             // (B,T,LAT)
    float* lvo   = muo  + (size_t)NROWS*LATD;             // (B,T,LAT)

    enc_persist_kernel<<<NBLK, 256>>>(x, eWih_f, eWhh_f, eb_f,
                                      eWih_b, eWhh_b, eb_b);

    encout_kernel<<<dim3(8, NROWS/128), 256>>>(Wout, bout, muo, lvo);

    zproj_kernel<<<NROWS/128, 256>>>(muo, lvo, eps, Wz, bz, zout);

    conductor_kernel<<<BB/16, 256>>>(zout, conWih, conWhh, conb);

    cudaFuncSetAttribute(decoder_kernel, cudaFuncAttributeMaxDynamicSharedMemorySize, 73728);
    decoder_kernel<<<(BB*TBAR)/8, 256, 73728>>>(x, dec_h0, dec_c0,
                                                dWih, dWhh, db, Wlin, blin, notes);
}